// round 16
// baseline (speedup 1.0000x reference)
#include <cuda_runtime.h>
#include <cuda_fp16.h>
#include <math.h>
#include <stddef.h>
#include <stdint.h>

#define D      1024
#define H      16
#define DH     64
#define NSEQ   2048
#define BATCH  4
#define ROWS   (BATCH*NSEQ)   /* 8192 */
#define BHN    (BATCH*H)      /* 64   */
#define TD     (3*D)          /* 3072 */
#define NC     (NSEQ/64)      /* 32 KV chunks */

// ---------------- scratch (all fp16 operands) --------------------------------
__device__ __half g_qkv[(size_t)ROWS * TD];        // 48 MB
__device__ __half g_attn[(size_t)ROWS * D];        // 16 MB
__device__ __half g_z  [(size_t)ROWS * D];         // 16 MB
__device__ __half g_wq [(size_t)TD * D];           //  6 MB  W_qkv^T [n][k]
__device__ __half g_wm [(size_t)D * D];            //  2 MB  W_msa^T [n][k]

// ---------------- helpers ----------------------------------------------------
__device__ __forceinline__ void mma_h(float* d, const uint32_t* a, const uint32_t* b) {
    asm volatile(
        "mma.sync.aligned.m16n8k16.row.col.f32.f16.f16.f32 "
        "{%0,%1,%2,%3}, {%4,%5,%6,%7}, {%8,%9}, {%0,%1,%2,%3};"
        : "+f"(d[0]), "+f"(d[1]), "+f"(d[2]), "+f"(d[3])
        : "r"(a[0]), "r"(a[1]), "r"(a[2]), "r"(a[3]), "r"(b[0]), "r"(b[1]));
}

__device__ __forceinline__ void ldsm4(uint32_t* d, uint32_t addr) {
    asm volatile("ldmatrix.sync.aligned.m8n8.x4.shared.b16 {%0,%1,%2,%3}, [%4];"
        : "=r"(d[0]), "=r"(d[1]), "=r"(d[2]), "=r"(d[3]) : "r"(addr));
}
// transposed variant: loads [tok][dh] tiles, yields V^T (B-operand) fragments
__device__ __forceinline__ void ldsm4t(uint32_t* d, uint32_t addr) {
    asm volatile("ldmatrix.sync.aligned.m8n8.x4.trans.shared.b16 {%0,%1,%2,%3}, [%4];"
        : "=r"(d[0]), "=r"(d[1]), "=r"(d[2]), "=r"(d[3]) : "r"(addr));
}

__device__ __forceinline__ float ex2f(float x) {
    float r;
    asm("ex2.approx.f32 %0, %1;" : "=f"(r) : "f"(x));
    return r;
}

__device__ __forceinline__ void cp16(uint32_t dst, const void* src) {
    asm volatile("cp.async.cg.shared.global [%0], [%1], 16;" :: "r"(dst), "l"(src));
}
__device__ __forceinline__ void cp_commit() {
    asm volatile("cp.async.commit_group;" ::: "memory");
}
__device__ __forceinline__ void cp_wait1() {
    asm volatile("cp.async.wait_group 1;" ::: "memory");
}
__device__ __forceinline__ void cp_wait2() {
    asm volatile("cp.async.wait_group 2;" ::: "memory");
}

// ---------------- prep kernels -----------------------------------------------
__global__ __launch_bounds__(256) void h_convert(
    const float* __restrict__ in, __half* __restrict__ out, int n4)
{
    int i = blockIdx.x * 256 + threadIdx.x;
    if (i < n4) {
        float4 v = ((const float4*)in)[i];
        ((__half2*)out)[2 * i]     = __floats2half2_rn(v.x, v.y);
        ((__half2*)out)[2 * i + 1] = __floats2half2_rn(v.z, v.w);
    }
}

__global__ __launch_bounds__(256) void trw_h(
    const float* __restrict__ W, __half* __restrict__ Wt, int Kd, int Nd)
{
    __shared__ float t[32][33];
    int k0 = blockIdx.x * 32, n0 = blockIdx.y * 32;
    int tx = threadIdx.x, ty = threadIdx.y;
#pragma unroll
    for (int i = 0; i < 4; i++)
        t[ty + i * 8][tx] = W[(size_t)(k0 + ty + i * 8) * Nd + n0 + tx];
    __syncthreads();
#pragma unroll
    for (int i = 0; i < 4; i++)
        Wt[(size_t)(n0 + ty + i * 8) * Kd + k0 + tx] = __float2half_rn(t[tx][ty + i * 8]);
}

// ---------------- fp16 GEMM: 3-stage cp.async + ldmatrix (proven R13) --------
#define GH_ROWB 144
#define GH_ASZ  (128*GH_ROWB)        /* 18432 */
#define GH_STG  (2*GH_ASZ)           /* 36864 */
#define GH_SMEM (3*GH_STG)           /* 110592 */

__global__ __launch_bounds__(256, 2) void gemm_h(
    int M, int N, int K,
    const __half* __restrict__ A, int lda,
    const __half* __restrict__ Bt, int ldb,
    __half* __restrict__ Ch, float* __restrict__ Cf, int ldc,
    const float* __restrict__ bias, int qkv_mode)
{
    extern __shared__ char smg[];
    uint32_t smb = (uint32_t)__cvta_generic_to_shared(smg);

    int tid  = threadIdx.x;
    int warp = tid >> 5, lane = tid & 31;
    int wm   = (warp >> 2) * 64;
    int wn   = (warp & 3) * 32;
    int bm   = blockIdx.y * 128;
    int bn   = blockIdx.x * 128;
    int q    = lane & 3;
    int r    = lane >> 2;

    int srow = tid >> 1;
    int sch0 = (tid & 1) * 4;

    float acc[4][4][4];
#pragma unroll
    for (int mt = 0; mt < 4; mt++)
#pragma unroll
        for (int nt = 0; nt < 4; nt++)
#pragma unroll
            for (int i = 0; i < 4; i++) acc[mt][nt][i] = 0.f;

    const __half* Ab = A  + (size_t)(bm + srow) * lda;
    const __half* Bb = Bt + (size_t)(bn + srow) * ldb;

    auto load_stage = [&](int st, int k0) {
        uint32_t ad = smb + (uint32_t)(st * GH_STG) + (uint32_t)srow * GH_ROWB;
        uint32_t bd = ad + (uint32_t)GH_ASZ;
#pragma unroll
        for (int i = 0; i < 4; i++) {
            int ch = sch0 + i;
            cp16(ad + ch * 16, Ab + k0 + ch * 8);
            cp16(bd + ch * 16, Bb + k0 + ch * 8);
        }
    };

    uint32_t a_row  = wm + (lane & 7) + 8 * ((lane >> 3) & 1);
    uint32_t a_colb = 16 * (lane >> 4);
    uint32_t b_row  = wn + (lane & 7) + 8 * (lane >> 4);
    uint32_t b_colb = 16 * ((lane >> 3) & 1);

    int NT = K / 64;
    load_stage(0, 0);  cp_commit();
    load_stage(1, 64); cp_commit();

    for (int it = 0; it < NT; it++) {
        int st = it % 3;
        cp_wait1();
        __syncthreads();
        if (it + 2 < NT) load_stage((it + 2) % 3, (it + 2) * 64);
        cp_commit();

        uint32_t abase = smb + (uint32_t)(st * GH_STG);
        uint32_t bbase = abase + (uint32_t)GH_ASZ;

#pragma unroll
        for (int ks = 0; ks < 4; ks++) {
            uint32_t a[4][4];
#pragma unroll
            for (int mt = 0; mt < 4; mt++)
                ldsm4(a[mt], abase + (a_row + mt * 16) * GH_ROWB + ks * 32 + a_colb);
            uint32_t bb[2][4];
#pragma unroll
            for (int p = 0; p < 2; p++)
                ldsm4(bb[p], bbase + (b_row + p * 16) * GH_ROWB + ks * 32 + b_colb);
#pragma unroll
            for (int mt = 0; mt < 4; mt++)
#pragma unroll
                for (int nt = 0; nt < 4; nt++)
                    mma_h(acc[mt][nt], a[mt], &bb[nt >> 1][(nt & 1) * 2]);
        }
    }

#pragma unroll
    for (int mt = 0; mt < 4; mt++) {
        size_t row0 = (size_t)(bm + wm + mt * 16 + r);
#pragma unroll
        for (int nt = 0; nt < 4; nt++) {
            int col = bn + wn + nt * 8 + 2 * q;
            float b0 = bias[col], b1 = bias[col + 1];
            float v00 = acc[mt][nt][0] + b0, v01 = acc[mt][nt][1] + b1;
            float v10 = acc[mt][nt][2] + b0, v11 = acc[mt][nt][3] + b1;
            if (qkv_mode) {
                // fold (1/sqrt(DH)) * log2(e) into Q columns for exp2-softmax
                float sc = ((col % 192) < 64) ? 0.180336880f : 1.0f;
                v00 *= sc; v01 *= sc; v10 *= sc; v11 *= sc;
                *(__half2*)(Ch + row0 * ldc + col)       = __floats2half2_rn(v00, v01);
                *(__half2*)(Ch + (row0 + 8) * ldc + col) = __floats2half2_rn(v10, v11);
            } else {
                float2 o0 = make_float2(v00, v01), o1 = make_float2(v10, v11);
                *(float2*)(Cf + row0 * ldc + col)       = o0;
                *(float2*)(Cf + (row0 + 8) * ldc + col) = o1;
            }
        }
    }
}

// ---------------- fp16 flash attention: combined K|V tiles, trans-V ----------
// grid (16, 64), 256 thr = 8 warps, warp = 16 q-rows. 3-stage KV ring, one
// barrier/chunk. Each stage row = 128 halves: K[tok][0:64] | V[tok][0:64]
// loaded as ONE contiguous 256B cp.async segment from g_qkv (K at +DH, V at
// +2DH are adjacent). V^T fragments come from ldmatrix.trans on [tok][dh].
// Softmax in exp2 domain (log2e pre-folded into Q).
#define FH_ROWB 272                  /* 256B data + 16B pad; 68 words = 4 mod 32 */
#define FH_QROWB 144
#define FH_QP   (128*FH_QROWB)       /* 18432 */
#define FH_STG  (64*FH_ROWB)         /* 17408 */
#define FH_SMEM (FH_QP + 3*FH_STG)   /* 70656 */

__global__ __launch_bounds__(256, 2) void flash_h(
    const __half* __restrict__ qkv, __half* __restrict__ attn)
{
    extern __shared__ char smf[];
    uint32_t smb = (uint32_t)__cvta_generic_to_shared(smf);

    int bh = blockIdx.y;
    int b = bh >> 4, h = bh & 15;
    int q0 = blockIdx.x * 128;

    int tid  = threadIdx.x;
    int warp = tid >> 5, lane = tid & 31;
    int q = lane & 3, r = lane >> 2;
    int rb = warp * 16;

    const __half* base = qkv + (size_t)b * NSEQ * TD + h * (3 * DH);

    // ---- async-load Q tile (128 rows x 64 halves, 144B stride) ----
    {
        int row = tid >> 1;
        int ch0 = (tid & 1) * 4;
        const __half* Qp = base + (size_t)(q0 + row) * TD;
        uint32_t qd = smb + (uint32_t)row * FH_QROWB;
#pragma unroll
        for (int i = 0; i < 4; i++) {
            int ch = ch0 + i;
            cp16(qd + ch * 16, Qp + ch * 8);
        }
    }
    cp_commit();

    int kvrow = tid >> 2;            // 0..63 (token)
    int kvc0  = (tid & 3) * 4;       // 4 chunks of 16B each (16 per 256B row)

    auto load_kv = [&](int stg, int kt) {
        const __half* KVp = base + (size_t)(kt + kvrow) * TD + DH;  // K|V contiguous
        uint32_t d = smb + (uint32_t)(FH_QP + stg * FH_STG) + (uint32_t)kvrow * FH_ROWB;
#pragma unroll
        for (int i = 0; i < 4; i++) {
            int ch = kvc0 + i;
            cp16(d + ch * 16, KVp + ch * 8);
        }
    };

    load_kv(0, 0);  cp_commit();
    load_kv(1, 64); cp_commit();

    // ldmatrix per-lane address components
    uint32_t qa_row = rb + (lane & 7) + 8 * ((lane >> 3) & 1);
    uint32_t a_colb = 16 * (lane >> 4);
    uint32_t kb_row = (lane & 7) + 8 * (lane >> 4);          // K (B-operand, n=tok)
    uint32_t kb_colb = 16 * ((lane >> 3) & 1);
    uint32_t vt_row = (lane & 7) + 8 * ((lane >> 3) & 1);    // V trans (k=tok rows)
    uint32_t vt_colb = 16 * (lane >> 4);                     // dh sub-tile select

    cp_wait2();                       // Q group complete
    __syncthreads();

    uint32_t qf[4][4];
#pragma unroll
    for (int ks = 0; ks < 4; ks++)
        ldsm4(qf[ks], smb + qa_row * FH_QROWB + ks * 32 + a_colb);

    float o[8][4];
#pragma unroll
    for (int nt = 0; nt < 8; nt++)
#pragma unroll
        for (int i = 0; i < 4; i++) o[nt][i] = 0.f;
    float m0 = -1e30f, m1 = -1e30f, l0 = 0.f, l1 = 0.f;

    __syncthreads();                  // all warps have Q frags; QP -> P

    for (int c = 0; c < NC; c++) {
        int st = c % 3;
        cp_wait1();
        __syncthreads();              // stage st ready; chunk c-1 compute done
        if (c + 2 < NC) load_kv((c + 2) % 3, (c + 2) * 64);
        cp_commit();

        uint32_t kvbase = smb + (uint32_t)(FH_QP + st * FH_STG);

        // S' = (Q * 0.125*log2e) @ K^T   (exp2 domain)
        float s[8][4];
#pragma unroll
        for (int nt = 0; nt < 8; nt++)
#pragma unroll
            for (int i = 0; i < 4; i++) s[nt][i] = 0.f;

#pragma unroll
        for (int ks = 0; ks < 4; ks++) {
            uint32_t bb[4][4];
#pragma unroll
            for (int tp = 0; tp < 4; tp++)
                ldsm4(bb[tp], kvbase + (tp * 16 + kb_row) * FH_ROWB + ks * 32 + kb_colb);
#pragma unroll
            for (int nt = 0; nt < 8; nt++)
                mma_h(s[nt], qf[ks], &bb[nt >> 1][(nt & 1) * 2]);
        }

        // online softmax in exp2 domain
        float mx0 = -1e30f, mx1 = -1e30f;
#pragma unroll
        for (int nt = 0; nt < 8; nt++) {
            mx0 = fmaxf(mx0, fmaxf(s[nt][0], s[nt][1]));
            mx1 = fmaxf(mx1, fmaxf(s[nt][2], s[nt][3]));
        }
#pragma unroll
        for (int off = 1; off <= 2; off <<= 1) {
            mx0 = fmaxf(mx0, __shfl_xor_sync(0xffffffffu, mx0, off));
            mx1 = fmaxf(mx1, __shfl_xor_sync(0xffffffffu, mx1, off));
        }
        float mn0 = fmaxf(m0, mx0), mn1 = fmaxf(m1, mx1);
        float al0 = ex2f(m0 - mn0), al1 = ex2f(m1 - mn1);
        m0 = mn0; m1 = mn1;

        float sum0 = 0.f, sum1 = 0.f;
#pragma unroll
        for (int nt = 0; nt < 8; nt++) {
            float p0 = ex2f(s[nt][0] - m0);
            float p1 = ex2f(s[nt][1] - m0);
            float p2 = ex2f(s[nt][2] - m1);
            float p3 = ex2f(s[nt][3] - m1);
            sum0 += p0 + p1; sum1 += p2 + p3;
            uint32_t off0 = (uint32_t)(rb + r) * FH_QROWB + (nt * 8 + 2 * q) * 2;
            uint32_t off1 = (uint32_t)(rb + r + 8) * FH_QROWB + (nt * 8 + 2 * q) * 2;
            *(__half2*)(smf + off0) = __floats2half2_rn(p0, p1);
            *(__half2*)(smf + off1) = __floats2half2_rn(p2, p3);
        }
#pragma unroll
        for (int off = 1; off <= 2; off <<= 1) {
            sum0 += __shfl_xor_sync(0xffffffffu, sum0, off);
            sum1 += __shfl_xor_sync(0xffffffffu, sum1, off);
        }
        l0 = l0 * al0 + sum0;
        l1 = l1 * al1 + sum1;

#pragma unroll
        for (int nt = 0; nt < 8; nt++) {
            o[nt][0] *= al0; o[nt][1] *= al0;
            o[nt][2] *= al1; o[nt][3] *= al1;
        }
        __syncwarp();                 // P rows are warp-private

        // O += P @ V  (V^T fragments via ldmatrix.trans on [tok][dh] at +128B)
#pragma unroll
        for (int ks = 0; ks < 4; ks++) {
            uint32_t pa[4];
            ldsm4(pa, smb + qa_row * FH_QROWB + ks * 32 + a_colb);
            uint32_t vv[4][4];
#pragma unroll
            for (int j = 0; j < 4; j++)     // dh0 = 16*j
                ldsm4t(vv[j], kvbase + (ks * 16 + vt_row) * FH_ROWB
                               + 128 + j * 32 + vt_colb);
#pragma unroll
            for (int nt = 0; nt < 8; nt++)
                mma_h(o[nt], pa, &vv[nt >> 1][(nt & 1) * 2]);
        }
        // no bottom barrier: 3-stage ring makes the next overwrite safe
    }

    // normalize, store fp16 to [b, n, D]
    float inv0 = 1.f / l0, inv1 = 1.f / l1;
    size_t row0 = (size_t)(b * NSEQ + q0 + rb + r);
#pragma unroll
    for (int nt = 0; nt < 8; nt++) {
        int col = h * DH + nt * 8 + 2 * q;
        *(__half2*)(attn + row0 * D + col) =
            __floats2half2_rn(o[nt][0] * inv0, o[nt][1] * inv0);
        *(__half2*)(attn + (row0 + 8) * D + col) =
            __floats2half2_rn(o[nt][2] * inv1, o[nt][3] * inv1);
    }
}

// ---------------- launch -----------------------------------------------------
extern "C" void kernel_launch(void* const* d_in, const int* in_sizes, int n_in,
                              void* d_out, int out_size)
{
    const float* z     = (const float*)d_in[0];
    const float* W_qkv = (const float*)d_in[1];
    const float* b_qkv = (const float*)d_in[2];
    const float* W_msa = (const float*)d_in[3];
    const float* b_msa = (const float*)d_in[4];
    float* out = (float*)d_out;

    __half *p_qkv, *p_attn, *p_z, *p_wq, *p_wm;
    cudaGetSymbolAddress((void**)&p_qkv, g_qkv);
    cudaGetSymbolAddress((void**)&p_attn, g_attn);
    cudaGetSymbolAddress((void**)&p_z, g_z);
    cudaGetSymbolAddress((void**)&p_wq, g_wq);
    cudaGetSymbolAddress((void**)&p_wm, g_wm);

    cudaFuncSetAttribute(gemm_h,
                         cudaFuncAttributeMaxDynamicSharedMemorySize, GH_SMEM);
    cudaFuncSetAttribute(flash_h,
                         cudaFuncAttributeMaxDynamicSharedMemorySize, FH_SMEM);

    // 0) prep: z -> fp16; weights -> fp16 transposed [n][k]
    h_convert<<<(ROWS * D / 4 + 255) / 256, 256>>>(z, p_z, ROWS * D / 4);
    trw_h<<<dim3(D / 32, TD / 32), dim3(32, 8)>>>(W_qkv, p_wq, D, TD);
    trw_h<<<dim3(D / 32, D / 32), dim3(32, 8)>>>(W_msa, p_wm, D, D);

    // 1) QKV projection (fp16 out; Q cols pre-scaled by 0.125*log2e)
    gemm_h<<<dim3(TD / 128, ROWS / 128), 256, GH_SMEM>>>(
        ROWS, TD, D, p_z, D, p_wq, D, p_qkv, nullptr, TD, b_qkv, 1);

    // 2) fused flash attention -> fp16 [b, n, D]  (V read in-place from g_qkv)
    flash_h<<<dim3(NSEQ / 128, BHN), 256, FH_SMEM>>>(p_qkv, p_attn);

    // 3) output projection (fp32 final output)
    gemm_h<<<dim3(D / 128, ROWS / 128), 256, GH_SMEM>>>(
        ROWS, D, D, p_attn, D, p_wm, D, nullptr, out, D, b_msa, 0);
}

// round 17
// speedup vs baseline: 1.0767x; 1.0767x over previous
#include <cuda_runtime.h>
#include <cuda_fp16.h>
#include <math.h>
#include <stddef.h>
#include <stdint.h>

#define D      1024
#define H      16
#define DH     64
#define NSEQ   2048
#define BATCH  4
#define ROWS   (BATCH*NSEQ)   /* 8192 */
#define BHN    (BATCH*H)      /* 64   */
#define TD     (3*D)          /* 3072 */
#define NC     (NSEQ/64)      /* 32 KV chunks */

// ---------------- scratch (all fp16 operands) --------------------------------
__device__ __half g_qkv[(size_t)ROWS * TD];        // 48 MB
__device__ __half g_attn[(size_t)ROWS * D];        // 16 MB
__device__ __half g_z  [(size_t)ROWS * D];         // 16 MB
__device__ __half g_wq [(size_t)TD * D];           //  6 MB  W_qkv^T [n][k]
__device__ __half g_wm [(size_t)D * D];            //  2 MB  W_msa^T [n][k]
__device__ __half g_vT [(size_t)BHN * DH * NSEQ];  // 16 MB  V^T [bh][dh][tok]

// ---------------- helpers ----------------------------------------------------
__device__ __forceinline__ void mma_h(float* d, const uint32_t* a, const uint32_t* b) {
    asm volatile(
        "mma.sync.aligned.m16n8k16.row.col.f32.f16.f16.f32 "
        "{%0,%1,%2,%3}, {%4,%5,%6,%7}, {%8,%9}, {%0,%1,%2,%3};"
        : "+f"(d[0]), "+f"(d[1]), "+f"(d[2]), "+f"(d[3])
        : "r"(a[0]), "r"(a[1]), "r"(a[2]), "r"(a[3]), "r"(b[0]), "r"(b[1]));
}

__device__ __forceinline__ void ldsm4(uint32_t* d, uint32_t addr) {
    asm volatile("ldmatrix.sync.aligned.m8n8.x4.shared.b16 {%0,%1,%2,%3}, [%4];"
        : "=r"(d[0]), "=r"(d[1]), "=r"(d[2]), "=r"(d[3]) : "r"(addr));
}

__device__ __forceinline__ float ex2f(float x) {
    float r;
    asm("ex2.approx.f32 %0, %1;" : "=f"(r) : "f"(x));
    return r;
}
__device__ __forceinline__ uint32_t packh2(float a, float b) {
    __half2 h = __floats2half2_rn(a, b);
    return *reinterpret_cast<uint32_t*>(&h);
}

__device__ __forceinline__ void cp16(uint32_t dst, const void* src) {
    asm volatile("cp.async.cg.shared.global [%0], [%1], 16;" :: "r"(dst), "l"(src));
}
__device__ __forceinline__ void cp_commit() {
    asm volatile("cp.async.commit_group;" ::: "memory");
}
__device__ __forceinline__ void cp_wait1() {
    asm volatile("cp.async.wait_group 1;" ::: "memory");
}
__device__ __forceinline__ void cp_wait2() {
    asm volatile("cp.async.wait_group 2;" ::: "memory");
}

// ---------------- prep kernels -----------------------------------------------
__global__ __launch_bounds__(256) void h_convert(
    const float* __restrict__ in, __half* __restrict__ out, int n4)
{
    int i = blockIdx.x * 256 + threadIdx.x;
    if (i < n4) {
        float4 v = ((const float4*)in)[i];
        ((__half2*)out)[2 * i]     = __floats2half2_rn(v.x, v.y);
        ((__half2*)out)[2 * i + 1] = __floats2half2_rn(v.z, v.w);
    }
}

__global__ __launch_bounds__(256) void trw_h(
    const float* __restrict__ W, __half* __restrict__ Wt, int Kd, int Nd)
{
    __shared__ float t[32][33];
    int k0 = blockIdx.x * 32, n0 = blockIdx.y * 32;
    int tx = threadIdx.x, ty = threadIdx.y;
#pragma unroll
    for (int i = 0; i < 4; i++)
        t[ty + i * 8][tx] = W[(size_t)(k0 + ty + i * 8) * Nd + n0 + tx];
    __syncthreads();
#pragma unroll
    for (int i = 0; i < 4; i++)
        Wt[(size_t)(n0 + ty + i * 8) * Kd + k0 + tx] = __float2half_rn(t[tx][ty + i * 8]);
}

__global__ __launch_bounds__(256) void vT_h(const __half* __restrict__ qkv,
                                            __half* __restrict__ vT)
{
    __shared__ __half t[32][33];
    int bh = blockIdx.y >> 1;
    int dh0 = (blockIdx.y & 1) * 32;
    int t0 = blockIdx.x * 32;
    int b = bh >> 4, h = bh & 15;
    int tx = threadIdx.x, ty = threadIdx.y;
#pragma unroll
    for (int i = 0; i < 4; i++)
        t[ty + i * 8][tx] =
            qkv[(size_t)(b * NSEQ + t0 + ty + i * 8) * TD + h * (3 * DH) + 2 * DH + dh0 + tx];
    __syncthreads();
#pragma unroll
    for (int i = 0; i < 4; i++)
        vT[((size_t)bh * DH + dh0 + ty + i * 8) * NSEQ + t0 + tx] = t[tx][ty + i * 8];
}

// ---------------- fp16 GEMM: 3-stage cp.async + ldmatrix (proven R13) --------
#define GH_ROWB 144
#define GH_ASZ  (128*GH_ROWB)        /* 18432 */
#define GH_STG  (2*GH_ASZ)           /* 36864 */
#define GH_SMEM (3*GH_STG)           /* 110592 */

__global__ __launch_bounds__(256, 2) void gemm_h(
    int M, int N, int K,
    const __half* __restrict__ A, int lda,
    const __half* __restrict__ Bt, int ldb,
    __half* __restrict__ Ch, float* __restrict__ Cf, int ldc,
    const float* __restrict__ bias, int qkv_mode)
{
    extern __shared__ char smg[];
    uint32_t smb = (uint32_t)__cvta_generic_to_shared(smg);

    int tid  = threadIdx.x;
    int warp = tid >> 5, lane = tid & 31;
    int wm   = (warp >> 2) * 64;
    int wn   = (warp & 3) * 32;
    int bm   = blockIdx.y * 128;
    int bn   = blockIdx.x * 128;
    int q    = lane & 3;
    int r    = lane >> 2;

    int srow = tid >> 1;
    int sch0 = (tid & 1) * 4;

    float acc[4][4][4];
#pragma unroll
    for (int mt = 0; mt < 4; mt++)
#pragma unroll
        for (int nt = 0; nt < 4; nt++)
#pragma unroll
            for (int i = 0; i < 4; i++) acc[mt][nt][i] = 0.f;

    const __half* Ab = A  + (size_t)(bm + srow) * lda;
    const __half* Bb = Bt + (size_t)(bn + srow) * ldb;

    auto load_stage = [&](int st, int k0) {
        uint32_t ad = smb + (uint32_t)(st * GH_STG) + (uint32_t)srow * GH_ROWB;
        uint32_t bd = ad + (uint32_t)GH_ASZ;
#pragma unroll
        for (int i = 0; i < 4; i++) {
            int ch = sch0 + i;
            cp16(ad + ch * 16, Ab + k0 + ch * 8);
            cp16(bd + ch * 16, Bb + k0 + ch * 8);
        }
    };

    uint32_t a_row  = wm + (lane & 7) + 8 * ((lane >> 3) & 1);
    uint32_t a_colb = 16 * (lane >> 4);
    uint32_t b_row  = wn + (lane & 7) + 8 * (lane >> 4);
    uint32_t b_colb = 16 * ((lane >> 3) & 1);

    int NT = K / 64;
    load_stage(0, 0);  cp_commit();
    load_stage(1, 64); cp_commit();

    for (int it = 0; it < NT; it++) {
        int st = it % 3;
        cp_wait1();
        __syncthreads();
        if (it + 2 < NT) load_stage((it + 2) % 3, (it + 2) * 64);
        cp_commit();

        uint32_t abase = smb + (uint32_t)(st * GH_STG);
        uint32_t bbase = abase + (uint32_t)GH_ASZ;

#pragma unroll
        for (int ks = 0; ks < 4; ks++) {
            uint32_t a[4][4];
#pragma unroll
            for (int mt = 0; mt < 4; mt++)
                ldsm4(a[mt], abase + (a_row + mt * 16) * GH_ROWB + ks * 32 + a_colb);
            uint32_t bb[2][4];
#pragma unroll
            for (int p = 0; p < 2; p++)
                ldsm4(bb[p], bbase + (b_row + p * 16) * GH_ROWB + ks * 32 + b_colb);
#pragma unroll
            for (int mt = 0; mt < 4; mt++)
#pragma unroll
                for (int nt = 0; nt < 4; nt++)
                    mma_h(acc[mt][nt], a[mt], &bb[nt >> 1][(nt & 1) * 2]);
        }
    }

#pragma unroll
    for (int mt = 0; mt < 4; mt++) {
        size_t row0 = (size_t)(bm + wm + mt * 16 + r);
#pragma unroll
        for (int nt = 0; nt < 4; nt++) {
            int col = bn + wn + nt * 8 + 2 * q;
            float b0 = bias[col], b1 = bias[col + 1];
            float v00 = acc[mt][nt][0] + b0, v01 = acc[mt][nt][1] + b1;
            float v10 = acc[mt][nt][2] + b0, v11 = acc[mt][nt][3] + b1;
            if (qkv_mode) {
                // fold (1/sqrt(DH)) * log2(e) into Q columns for exp2-softmax
                float sc = ((col % 192) < 64) ? 0.180336880f : 1.0f;
                v00 *= sc; v01 *= sc; v10 *= sc; v11 *= sc;
                *(__half2*)(Ch + row0 * ldc + col)       = __floats2half2_rn(v00, v01);
                *(__half2*)(Ch + (row0 + 8) * ldc + col) = __floats2half2_rn(v10, v11);
            } else {
                float2 o0 = make_float2(v00, v01), o1 = make_float2(v10, v11);
                *(float2*)(Cf + row0 * ldc + col)       = o0;
                *(float2*)(Cf + (row0 + 8) * ldc + col) = o1;
            }
        }
    }
}

// ---------------- fp16 flash attention: P kept entirely in registers ---------
// grid (16, 64), 256 thr = 8 warps, warp = 16 q-rows. 3-stage KV ring, one
// barrier/chunk. S accumulator repacks DIRECTLY into the PV A-operand
// (register-local: S frag (r, nt*8+2q..) == A frag (r, ks*16+2q..) pairs).
// No P smem, no syncwarp. exp2-domain softmax (log2e folded into Q).
#define FH_ROWB 144
#define FH_QP   (128*FH_ROWB)        /* 18432 */
#define FH_KSZ  (64*FH_ROWB)         /*  9216 */
#define FH_STG  (2*FH_KSZ)           /* 18432 */
#define FH_SMEM (FH_QP + 3*FH_STG)   /* 73728 */

__global__ __launch_bounds__(256, 2) void flash_h(
    const __half* __restrict__ qkv, const __half* __restrict__ vT,
    __half* __restrict__ attn)
{
    extern __shared__ char smf[];
    uint32_t smb = (uint32_t)__cvta_generic_to_shared(smf);

    int bh = blockIdx.y;
    int b = bh >> 4, h = bh & 15;
    int q0 = blockIdx.x * 128;

    int tid  = threadIdx.x;
    int warp = tid >> 5, lane = tid & 31;
    int q = lane & 3, r = lane >> 2;
    int rb = warp * 16;

    const __half* base  = qkv + (size_t)b * NSEQ * TD + h * (3 * DH);
    const __half* vbase = vT + (size_t)bh * DH * NSEQ;

    // ---- async-load Q tile (128 rows x 64 halves) ----
    {
        int row = tid >> 1;
        int ch0 = (tid & 1) * 4;
        const __half* Qp = base + (size_t)(q0 + row) * TD;
        uint32_t qd = smb + (uint32_t)row * FH_ROWB;
#pragma unroll
        for (int i = 0; i < 4; i++) {
            int ch = ch0 + i;
            cp16(qd + ch * 16, Qp + ch * 8);
        }
    }
    cp_commit();

    int kvrow = tid >> 2;            // 0..63
    int kvc0  = (tid & 3) * 2;       // 2 chunks of 16B each for K and V

    auto load_kv = [&](int stg, int kt) {
        const __half* Kp = base + (size_t)(kt + kvrow) * TD + DH;
        const __half* Vp = vbase + (size_t)kvrow * NSEQ + kt;
        uint32_t kd = smb + (uint32_t)(FH_QP + stg * FH_STG) + (uint32_t)kvrow * FH_ROWB;
        uint32_t vd = kd + (uint32_t)FH_KSZ;
#pragma unroll
        for (int i = 0; i < 2; i++) {
            int ch = kvc0 + i;
            cp16(kd + ch * 16, Kp + ch * 8);
            cp16(vd + ch * 16, Vp + ch * 8);
        }
    };

    load_kv(0, 0);  cp_commit();
    load_kv(1, 64); cp_commit();

    uint32_t qa_row = rb + (lane & 7) + 8 * ((lane >> 3) & 1);
    uint32_t a_colb = 16 * (lane >> 4);
    uint32_t kb_row = (lane & 7) + 8 * (lane >> 4);
    uint32_t b_colb = 16 * ((lane >> 3) & 1);

    cp_wait2();                       // Q group complete
    __syncthreads();

    uint32_t qf[4][4];
#pragma unroll
    for (int ks = 0; ks < 4; ks++)
        ldsm4(qf[ks], smb + qa_row * FH_ROWB + ks * 32 + a_colb);

    float o[8][4];
#pragma unroll
    for (int nt = 0; nt < 8; nt++)
#pragma unroll
        for (int i = 0; i < 4; i++) o[nt][i] = 0.f;
    float m0 = -1e30f, m1 = -1e30f, l0 = 0.f, l1 = 0.f;

    __syncthreads();

    for (int c = 0; c < NC; c++) {
        int st = c % 3;
        cp_wait1();
        __syncthreads();              // stage st ready; chunk c-1 compute done
        if (c + 2 < NC) load_kv((c + 2) % 3, (c + 2) * 64);
        cp_commit();

        uint32_t kbase = smb + (uint32_t)(FH_QP + st * FH_STG);
        uint32_t vbse  = kbase + (uint32_t)FH_KSZ;

        // S' = (Q * 0.125*log2e) @ K^T
        float s[8][4];
#pragma unroll
        for (int nt = 0; nt < 8; nt++)
#pragma unroll
            for (int i = 0; i < 4; i++) s[nt][i] = 0.f;

#pragma unroll
        for (int ks = 0; ks < 4; ks++) {
            uint32_t bb[4][4];
#pragma unroll
            for (int tp = 0; tp < 4; tp++)
                ldsm4(bb[tp], kbase + (tp * 16 + kb_row) * FH_ROWB + ks * 32 + b_colb);
#pragma unroll
            for (int nt = 0; nt < 8; nt++)
                mma_h(s[nt], qf[ks], &bb[nt >> 1][(nt & 1) * 2]);
        }

        // online softmax in exp2 domain; pack P straight into PV A-fragments
        float mx0 = -1e30f, mx1 = -1e30f;
#pragma unroll
        for (int nt = 0; nt < 8; nt++) {
            mx0 = fmaxf(mx0, fmaxf(s[nt][0], s[nt][1]));
            mx1 = fmaxf(mx1, fmaxf(s[nt][2], s[nt][3]));
        }
#pragma unroll
        for (int off = 1; off <= 2; off <<= 1) {
            mx0 = fmaxf(mx0, __shfl_xor_sync(0xffffffffu, mx0, off));
            mx1 = fmaxf(mx1, __shfl_xor_sync(0xffffffffu, mx1, off));
        }
        float mn0 = fmaxf(m0, mx0), mn1 = fmaxf(m1, mx1);
        float al0 = ex2f(m0 - mn0), al1 = ex2f(m1 - mn1);
        m0 = mn0; m1 = mn1;

        uint32_t pa[4][4];            // PV A-operand fragments (register-local)
        float sum0 = 0.f, sum1 = 0.f;
#pragma unroll
        for (int nt = 0; nt < 8; nt++) {
            float p0 = ex2f(s[nt][0] - m0);
            float p1 = ex2f(s[nt][1] - m0);
            float p2 = ex2f(s[nt][2] - m1);
            float p3 = ex2f(s[nt][3] - m1);
            sum0 += p0 + p1; sum1 += p2 + p3;
            int ks = nt >> 1, half = (nt & 1) * 2;
            pa[ks][half]     = packh2(p0, p1);   // rows r    : a0 / a2
            pa[ks][half + 1] = packh2(p2, p3);   // rows r+8  : a1 / a3
        }
#pragma unroll
        for (int off = 1; off <= 2; off <<= 1) {
            sum0 += __shfl_xor_sync(0xffffffffu, sum0, off);
            sum1 += __shfl_xor_sync(0xffffffffu, sum1, off);
        }
        l0 = l0 * al0 + sum0;
        l1 = l1 * al1 + sum1;

#pragma unroll
        for (int nt = 0; nt < 8; nt++) {
            o[nt][0] *= al0; o[nt][1] *= al0;
            o[nt][2] *= al1; o[nt][3] *= al1;
        }

        // O += P @ V   (V^T in [dh][tok] layout; P already in registers)
#pragma unroll
        for (int ks = 0; ks < 4; ks++) {
            uint32_t bb[4][4];
#pragma unroll
            for (int tp = 0; tp < 4; tp++)
                ldsm4(bb[tp], vbse + (tp * 16 + kb_row) * FH_ROWB + ks * 32 + b_colb);
#pragma unroll
            for (int nt = 0; nt < 8; nt++)
                mma_h(o[nt], pa[ks], &bb[nt >> 1][(nt & 1) * 2]);
        }
        // no bottom barrier: 3-stage ring makes the next overwrite safe
    }

    // normalize, store fp16 to [b, n, D]
    float inv0 = 1.f / l0, inv1 = 1.f / l1;
    size_t row0 = (size_t)(b * NSEQ + q0 + rb + r);
#pragma unroll
    for (int nt = 0; nt < 8; nt++) {
        int col = h * DH + nt * 8 + 2 * q;
        *(__half2*)(attn + row0 * D + col) =
            __floats2half2_rn(o[nt][0] * inv0, o[nt][1] * inv0);
        *(__half2*)(attn + (row0 + 8) * D + col) =
            __floats2half2_rn(o[nt][2] * inv1, o[nt][3] * inv1);
    }
}

// ---------------- launch -----------------------------------------------------
extern "C" void kernel_launch(void* const* d_in, const int* in_sizes, int n_in,
                              void* d_out, int out_size)
{
    const float* z     = (const float*)d_in[0];
    const float* W_qkv = (const float*)d_in[1];
    const float* b_qkv = (const float*)d_in[2];
    const float* W_msa = (const float*)d_in[3];
    const float* b_msa = (const float*)d_in[4];
    float* out = (float*)d_out;

    __half *p_qkv, *p_attn, *p_z, *p_wq, *p_wm, *p_vT;
    cudaGetSymbolAddress((void**)&p_qkv, g_qkv);
    cudaGetSymbolAddress((void**)&p_attn, g_attn);
    cudaGetSymbolAddress((void**)&p_z, g_z);
    cudaGetSymbolAddress((void**)&p_wq, g_wq);
    cudaGetSymbolAddress((void**)&p_wm, g_wm);
    cudaGetSymbolAddress((void**)&p_vT, g_vT);

    cudaFuncSetAttribute(gemm_h,
                         cudaFuncAttributeMaxDynamicSharedMemorySize, GH_SMEM);
    cudaFuncSetAttribute(flash_h,
                         cudaFuncAttributeMaxDynamicSharedMemorySize, FH_SMEM);

    // 0) prep: z -> fp16; weights -> fp16 transposed [n][k]
    h_convert<<<(ROWS * D / 4 + 255) / 256, 256>>>(z, p_z, ROWS * D / 4);
    trw_h<<<dim3(D / 32, TD / 32), dim3(32, 8)>>>(W_qkv, p_wq, D, TD);
    trw_h<<<dim3(D / 32, D / 32), dim3(32, 8)>>>(W_msa, p_wm, D, D);

    // 1) QKV projection (fp16 out; Q cols pre-scaled by 0.125*log2e)
    gemm_h<<<dim3(TD / 128, ROWS / 128), 256, GH_SMEM>>>(
        ROWS, TD, D, p_z, D, p_wq, D, p_qkv, nullptr, TD, b_qkv, 1);

    // 1b) V^T into [bh][dh][tok]
    vT_h<<<dim3(NSEQ / 32, 2 * BHN), dim3(32, 8)>>>(p_qkv, p_vT);

    // 2) fused flash attention -> fp16 [b, n, D]
    flash_h<<<dim3(NSEQ / 128, BHN), 256, FH_SMEM>>>(p_qkv, p_vT, p_attn);

    // 3) output projection (fp32 final output)
    gemm_h<<<dim3(D / 128, ROWS / 128), 256, GH_SMEM>>>(
        ROWS, D, D, p_attn, D, p_wm, D, nullptr, out, D, b_msa, 0);
}